// round 1
// baseline (speedup 1.0000x reference)
#include <cuda_runtime.h>
#include <cuda_bf16.h>

// Problem constants
#define BATCH 256
#define SEQ   256
#define EMB   256
#define HID   1024
#define GATES 4096          // 4*HID
#define SH    (SEQ * HID)   // 262144

// Precomputed projection tables:
//   g_lp[l][g] = sum_k letter_emb[l][k] * W_ih[g][k]            (30 x 4096)
//   g_sp[s][g] = sum_k state_emb[s][k] * W_ih[g][256+k] + b_ih[g] + b_hh[g]
__device__ float g_lp[30 * GATES];
__device__ float g_sp[4 * GATES];

// ---------------------------------------------------------------------------
// f32x2 packed-FMA helpers (sm_103a FFMA2 path)
// ---------------------------------------------------------------------------
__device__ __forceinline__ void fma2(unsigned long long& d,
                                     unsigned long long a,
                                     unsigned long long b) {
    asm("fma.rn.f32x2 %0, %1, %2, %0;" : "+l"(d) : "l"(a), "l"(b));
}
__device__ __forceinline__ unsigned long long pack2(float x) {
    unsigned long long r;
    asm("mov.b64 %0, {%1, %1};" : "=l"(r) : "f"(x));
    return r;
}
__device__ __forceinline__ float2 unpack2(unsigned long long v) {
    float2 f;
    asm("mov.b64 {%0, %1}, %2;" : "=f"(f.x), "=f"(f.y) : "l"(v));
    return f;
}

__device__ __forceinline__ float sigmoidf_(float x) {
    return 1.0f / (1.0f + expf(-x));
}

// ---------------------------------------------------------------------------
// Kernel A: tiny projection-table precompute (~70 MFLOP, runs once)
// ---------------------------------------------------------------------------
__global__ void proj_kernel(const float* __restrict__ letter_emb,
                            const float* __restrict__ state_emb,
                            const float* __restrict__ W_ih,
                            const float* __restrict__ b_ih,
                            const float* __restrict__ b_hh) {
    int g = blockIdx.x * blockDim.x + threadIdx.x;
    if (g >= GATES) return;
    const float* wl = W_ih + (size_t)g * (2 * EMB);        // letter part
    const float* ws = wl + EMB;                            // state part

    for (int l = 0; l < 30; ++l) {
        const float* e = letter_emb + l * EMB;
        float s = 0.0f;
        #pragma unroll 8
        for (int k = 0; k < EMB; ++k) s += e[k] * wl[k];
        g_lp[l * GATES + g] = s;
    }
    float bias = b_ih[g] + b_hh[g];
    for (int st = 0; st < 4; ++st) {
        const float* e = state_emb + st * EMB;
        float s = bias;
        #pragma unroll 8
        for (int k = 0; k < EMB; ++k) s += e[k] * ws[k];
        g_sp[st * GATES + g] = s;
    }
}

// ---------------------------------------------------------------------------
// Kernel B: one LSTM timestep.
//   gates[b][g] = table_base + sum_k h_prev[b][k] * W_hh[g][k]
// CTA tile: 64 batch x 32 h-cols, all 4 gates fused.
// Thread micro-tile: 4 batch x 2 j (packed f32x2) x 4 gates = 16 u64 accs.
// h_prev / c_prev read from previous step's slice of d_out.
// ---------------------------------------------------------------------------
#define BM 64
#define BJ 32
#define KT 16

__global__ void __launch_bounds__(256)
step_kernel(const int* __restrict__ lseq,
            const int* __restrict__ sseq,
            const float* __restrict__ W_hh,
            float* __restrict__ out,   // [hidden | cell], each [B][S][H]
            int t) {
    __shared__ float As[BM][KT + 1];        // h tile: [b][k], padded
    __shared__ float Bs[4][KT][BJ + 2];     // W tile: [gate][k][j], +2 keeps 8B align & kills conflicts

    const int tid = threadIdx.x;
    const int tx = tid & 15;                // j pair index (16)
    const int ty = tid >> 4;                // b quad index (16)
    const int b0 = blockIdx.y * BM;
    const int j0 = blockIdx.x * BJ;

    float* __restrict__ out_h = out;
    float* __restrict__ out_c = out + (size_t)BATCH * SH;

    unsigned long long acc[4][4];           // [b_micro][gate], each packs 2 j
    #pragma unroll
    for (int i = 0; i < 4; ++i)
        #pragma unroll
        for (int g = 0; g < 4; ++g) acc[i][g] = 0ull;

    if (t > 0) {
        const float* hprev_base = out_h + (size_t)(t - 1) * HID;  // + b*SH + k
        const int arow = tid >> 2;          // 0..63  (batch row in tile)
        const int akq  = tid & 3;           // float4 chunk along k

        for (int k0 = 0; k0 < HID; k0 += KT) {
            __syncthreads();
            // --- load A tile: 64 x 16 of h_prev ---
            {
                float4 v = *reinterpret_cast<const float4*>(
                    hprev_base + (size_t)(b0 + arow) * SH + k0 + akq * 4);
                As[arow][akq * 4 + 0] = v.x;
                As[arow][akq * 4 + 1] = v.y;
                As[arow][akq * 4 + 2] = v.z;
                As[arow][akq * 4 + 3] = v.w;
            }
            // --- load B tile: 4 gates x 32 j x 16 k of W_hh ---
            #pragma unroll
            for (int it = 0; it < 2; ++it) {
                int idx = tid + it * 256;       // 0..511
                int g   = idx >> 7;             // gate
                int r   = idx & 127;
                int jr  = r >> 2;               // j row 0..31
                int kq  = r & 3;                // float4 chunk
                float4 v = *reinterpret_cast<const float4*>(
                    W_hh + (size_t)(g * HID + j0 + jr) * HID + k0 + kq * 4);
                Bs[g][kq * 4 + 0][jr] = v.x;
                Bs[g][kq * 4 + 1][jr] = v.y;
                Bs[g][kq * 4 + 2][jr] = v.z;
                Bs[g][kq * 4 + 3][jr] = v.w;
            }
            __syncthreads();

            // --- FFMA2 inner loop ---
            #pragma unroll
            for (int kk = 0; kk < KT; ++kk) {
                unsigned long long w[4];
                #pragma unroll
                for (int g = 0; g < 4; ++g)
                    w[g] = *reinterpret_cast<const unsigned long long*>(
                        &Bs[g][kk][tx * 2]);
                #pragma unroll
                for (int i = 0; i < 4; ++i) {
                    unsigned long long a2 = pack2(As[ty * 4 + i][kk]);
                    #pragma unroll
                    for (int g = 0; g < 4; ++g) fma2(acc[i][g], a2, w[g]);
                }
            }
        }
    }

    // --- epilogue: gate nonlinearities + cell update ---
    #pragma unroll
    for (int i = 0; i < 4; ++i) {
        const int b = b0 + ty * 4 + i;
        const int l  = lseq[b * SEQ + t];
        const int st = sseq[b * SEQ + t];
        const float* lp = g_lp + (size_t)l * GATES;
        const float* sp = g_sp + (size_t)st * GATES;
        float2 z[4];
        #pragma unroll
        for (int g = 0; g < 4; ++g) z[g] = unpack2(acc[i][g]);

        #pragma unroll
        for (int jj = 0; jj < 2; ++jj) {
            const int j = j0 + tx * 2 + jj;
            float zi = (jj ? z[0].y : z[0].x) + lp[0 * HID + j] + sp[0 * HID + j];
            float zf = (jj ? z[1].y : z[1].x) + lp[1 * HID + j] + sp[1 * HID + j];
            float zg = (jj ? z[2].y : z[2].x) + lp[2 * HID + j] + sp[2 * HID + j];
            float zo = (jj ? z[3].y : z[3].x) + lp[3 * HID + j] + sp[3 * HID + j];

            float ig = sigmoidf_(zi);
            float fg = sigmoidf_(zf);
            float gg = tanhf(zg);
            float og = sigmoidf_(zo);

            float cp = (t > 0) ? out_c[(size_t)b * SH + (size_t)(t - 1) * HID + j]
                               : 0.0f;
            float c = fg * cp + ig * gg;
            float h = og * tanhf(c);

            size_t oidx = (size_t)b * SH + (size_t)t * HID + j;
            out_h[oidx] = h;
            out_c[oidx] = c;
        }
    }
}

// ---------------------------------------------------------------------------
extern "C" void kernel_launch(void* const* d_in, const int* in_sizes, int n_in,
                              void* d_out, int out_size) {
    const int*   lseq  = (const int*)d_in[0];
    const int*   sseq  = (const int*)d_in[1];
    const float* lemb  = (const float*)d_in[2];
    const float* semb  = (const float*)d_in[3];
    const float* W_ih  = (const float*)d_in[4];
    const float* W_hh  = (const float*)d_in[5];
    const float* b_ih  = (const float*)d_in[6];
    const float* b_hh  = (const float*)d_in[7];
    float* out = (float*)d_out;

    proj_kernel<<<(GATES + 127) / 128, 128>>>(lemb, semb, W_ih, b_ih, b_hh);

    dim3 grid(HID / BJ, BATCH / BM);   // 32 x 4 = 128 CTAs
    for (int t = 0; t < SEQ; ++t)
        step_kernel<<<grid, 256>>>(lseq, sseq, W_hh, out, t);
}

// round 3
// speedup vs baseline: 3.1785x; 3.1785x over previous
#include <cuda_runtime.h>
#include <cuda_bf16.h>
#include <cstdint>

// ---------------------------------------------------------------------------
// Problem constants
// ---------------------------------------------------------------------------
#define BATCH 256
#define SEQ   256
#define EMB   256
#define HID   1024
#define GATES 4096          // 4*HID
#define SH    (SEQ * HID)   // per-batch stride in out

// GEMM tiling
#define TM 64               // CTA M tile (batch)
#define TN 128              // CTA N tile (gate-cols, j-major)
#define KC 64               // K chunk (bf16)
#define NCHUNK (HID / KC)   // 16

// SMEM stage layout: Ah | Al | Bh | Bl
#define OFF_AH 0
#define OFF_AL 8192         // 64*64*2
#define OFF_BH 16384
#define OFF_BL 32768        // Bh = 128*64*2 = 16384
#define STAGE  49152
#define SMEM_TOTAL (2 * STAGE)   // 96 KB; epilogue D aliases stage 0

#define DS 132              // D smem row stride (floats)

// ---------------------------------------------------------------------------
// Device-global precomputed state
// ---------------------------------------------------------------------------
__device__ float g_lp_r[30 * GATES];   // n = j*4 + gate
__device__ float g_sp_r[4 * GATES];
__device__ __nv_bfloat16 g_W_hi[(size_t)GATES * HID];   // row n = j*4+g
__device__ __nv_bfloat16 g_W_lo[(size_t)GATES * HID];
__device__ __nv_bfloat16 g_h_hi[2][(size_t)BATCH * HID];
__device__ __nv_bfloat16 g_h_lo[2][(size_t)BATCH * HID];

// ---------------------------------------------------------------------------
// PTX helpers (all Ampere-era: valid at compute_103)
// ---------------------------------------------------------------------------
__device__ __forceinline__ uint32_t smem_u32(const void* p) {
    uint32_t a;
    asm("{ .reg .u64 t; cvta.to.shared.u64 t, %1; cvt.u32.u64 %0, t; }"
        : "=r"(a) : "l"(p));
    return a;
}
#define CP16(dst, src) \
    asm volatile("cp.async.cg.shared.global [%0], [%1], 16;" :: "r"(dst), "l"(src))
#define CP_COMMIT() asm volatile("cp.async.commit_group;" ::: "memory")
#define CP_WAIT(n)  asm volatile("cp.async.wait_group %0;" :: "n"(n) : "memory")

__device__ __forceinline__ void ldsm_x4(uint32_t (&r)[4], uint32_t addr) {
    asm volatile("ldmatrix.sync.aligned.m8n8.x4.shared.b16 {%0,%1,%2,%3}, [%4];"
                 : "=r"(r[0]), "=r"(r[1]), "=r"(r[2]), "=r"(r[3]) : "r"(addr));
}
__device__ __forceinline__ void mma_bf16(float (&d)[4], const uint32_t (&a)[4],
                                         const uint32_t* b) {
    asm volatile(
        "mma.sync.aligned.m16n8k16.row.col.f32.bf16.bf16.f32 "
        "{%0,%1,%2,%3}, {%4,%5,%6,%7}, {%8,%9}, {%0,%1,%2,%3};"
        : "+f"(d[0]), "+f"(d[1]), "+f"(d[2]), "+f"(d[3])
        : "r"(a[0]), "r"(a[1]), "r"(a[2]), "r"(a[3]), "r"(b[0]), "r"(b[1]));
}

__device__ __forceinline__ float sigf(float x) {
    float e = __expf(-x);
    return __fdividef(1.0f, 1.0f + e);
}
__device__ __forceinline__ float tanh_(float x) {
    float e = __expf(-2.0f * x);
    return __fdividef(1.0f - e, 1.0f + e);
}

// ---------------------------------------------------------------------------
// Precompute 1: reordered projection tables
// ---------------------------------------------------------------------------
__global__ void proj_kernel(const float* __restrict__ letter_emb,
                            const float* __restrict__ state_emb,
                            const float* __restrict__ W_ih,
                            const float* __restrict__ b_ih,
                            const float* __restrict__ b_hh) {
    int r = blockIdx.x * blockDim.x + threadIdx.x;
    if (r >= GATES) return;
    int gate = r / HID, j = r % HID;
    int n = j * 4 + gate;
    const float* wl = W_ih + (size_t)r * (2 * EMB);
    const float* ws = wl + EMB;

    for (int l = 0; l < 30; ++l) {
        const float* e = letter_emb + l * EMB;
        float s = 0.0f;
        #pragma unroll 8
        for (int k = 0; k < EMB; ++k) s += e[k] * wl[k];
        g_lp_r[l * GATES + n] = s;
    }
    float bias = b_ih[r] + b_hh[r];
    for (int st = 0; st < 4; ++st) {
        const float* e = state_emb + st * EMB;
        float s = bias;
        #pragma unroll 8
        for (int k = 0; k < EMB; ++k) s += e[k] * ws[k];
        g_sp_r[st * GATES + n] = s;
    }
}

// ---------------------------------------------------------------------------
// Precompute 2: W_hh reorder + bf16 hi/lo split
// ---------------------------------------------------------------------------
__global__ void wsplit_kernel(const float* __restrict__ W_hh) {
    size_t idx = (size_t)blockIdx.x * blockDim.x + threadIdx.x;
    size_t total = (size_t)GATES * HID;
    for (; idx < total; idx += (size_t)gridDim.x * blockDim.x) {
        int n = (int)(idx >> 10);
        int k = (int)(idx & 1023);
        int j = n >> 2, g = n & 3;
        float w = W_hh[((size_t)g * HID + j) * HID + k];
        __nv_bfloat16 hi = __float2bfloat16(w);
        g_W_hi[idx] = hi;
        g_W_lo[idx] = __float2bfloat16(w - __bfloat162float(hi));
    }
}

// ---------------------------------------------------------------------------
// One LSTM timestep via warp-level bf16x3 HMMA
// ---------------------------------------------------------------------------
__global__ void __launch_bounds__(256, 1)
step_kernel(const int* __restrict__ lseq,
            const int* __restrict__ sseq,
            float* __restrict__ out, int t) {
    extern __shared__ char smem[];
    const int tid  = threadIdx.x;
    const int wid  = tid >> 5;
    const int lane = tid & 31;
    const int wm   = wid >> 2;     // 0..1
    const int wn   = wid & 3;      // 0..3
    const int m0   = blockIdx.y * TM;
    const int n0c  = blockIdx.x * TN;
    const int j0   = n0c >> 2;

    float* __restrict__ out_h = out;
    float* __restrict__ out_c = out + (size_t)BATCH * SH;
    __nv_bfloat16* __restrict__ hw_hi = g_h_hi[t & 1];
    __nv_bfloat16* __restrict__ hw_lo = g_h_lo[t & 1];

    if (t == 0) {
        for (int u = tid; u < TM * 32; u += 256) {
            int r = u >> 5, q = u & 31;
            int b = m0 + r, j = j0 + q;
            int l  = lseq[b * SEQ];
            int st = sseq[b * SEQ];
            const float4 L = *(const float4*)&g_lp_r[(size_t)l  * GATES + (size_t)j * 4];
            const float4 S = *(const float4*)&g_sp_r[(size_t)st * GATES + (size_t)j * 4];
            float ig = sigf(L.x + S.x);
            float gg = tanh_(L.z + S.z);
            float og = sigf(L.w + S.w);
            float c = ig * gg;
            float h = og * tanh_(c);
            out_h[(size_t)b * SH + j] = h;
            out_c[(size_t)b * SH + j] = c;
            __nv_bfloat16 hh = __float2bfloat16(h);
            hw_hi[(size_t)b * HID + j] = hh;
            hw_lo[(size_t)b * HID + j] = __float2bfloat16(h - __bfloat162float(hh));
        }
        return;
    }

    const uint32_t sb = smem_u32(smem);
    const __nv_bfloat16* __restrict__ ha_hi = g_h_hi[(t & 1) ^ 1] + (size_t)m0 * HID;
    const __nv_bfloat16* __restrict__ ha_lo = g_h_lo[(t & 1) ^ 1] + (size_t)m0 * HID;
    const __nv_bfloat16* __restrict__ wb_hi = g_W_hi + (size_t)n0c * HID;
    const __nv_bfloat16* __restrict__ wb_lo = g_W_lo + (size_t)n0c * HID;

    float acc[2][4][4];
    #pragma unroll
    for (int ms = 0; ms < 2; ++ms)
        #pragma unroll
        for (int ns = 0; ns < 4; ++ns)
            #pragma unroll
            for (int q = 0; q < 4; ++q) acc[ms][ns][q] = 0.0f;

    // chunk loader: 12 x 16B cp.async per thread
    auto load_chunk = [&](uint32_t buf, int k0) {
        // A tiles (64 x 64): 512 chunks each
        #pragma unroll
        for (int i = 0; i < 2; ++i) {
            int id = tid + i * 256;
            int r = id >> 3, c = id & 7;
            uint32_t dst = buf + (uint32_t)(r * 128 + ((c ^ (r & 7)) << 4));
            CP16(dst + OFF_AH, ha_hi + (size_t)r * HID + k0 + c * 8);
            CP16(dst + OFF_AL, ha_lo + (size_t)r * HID + k0 + c * 8);
        }
        // B tiles (128 x 64): 1024 chunks each
        #pragma unroll
        for (int i = 0; i < 4; ++i) {
            int id = tid + i * 256;
            int r = id >> 3, c = id & 7;
            uint32_t dst = buf + (uint32_t)(r * 128 + ((c ^ (r & 7)) << 4));
            CP16(dst + OFF_BH, wb_hi + (size_t)r * HID + k0 + c * 8);
            CP16(dst + OFF_BL, wb_lo + (size_t)r * HID + k0 + c * 8);
        }
    };

    load_chunk(sb, 0);
    CP_COMMIT();

    for (int kc = 0; kc < NCHUNK; ++kc) {
        if (kc < NCHUNK - 1) {
            load_chunk(sb + ((kc + 1) & 1) * STAGE, (kc + 1) * KC);
            CP_COMMIT();
            CP_WAIT(1);
        } else {
            CP_WAIT(0);
        }
        __syncthreads();

        const uint32_t base = sb + (kc & 1) * STAGE;
        #pragma unroll
        for (int k16 = 0; k16 < 4; ++k16) {
            // ---- A frags: m16 x k16, 2 m-frags x {hi,lo} ----
            uint32_t ah[2][4], al[2][4];
            {
                const int g = lane >> 3, lr = lane & 7;
                #pragma unroll
                for (int ms = 0; ms < 2; ++ms) {
                    int r = wm * 32 + ms * 16 + lr + ((g & 1) << 3);
                    int c16 = k16 * 2 + (g >> 1);
                    uint32_t ad = base + (uint32_t)(r * 128 + ((c16 ^ (r & 7)) << 4));
                    ldsm_x4(ah[ms], ad + OFF_AH);
                    ldsm_x4(al[ms], ad + OFF_AL);
                }
            }
            // ---- B frags: 4 n8-frags per split, 2 frags per ldsm.x4 ----
            uint32_t bh[4][2], bl[4][2];
            {
                const int g = lane >> 3, lr = lane & 7;
                #pragma unroll
                for (int np = 0; np < 2; ++np) {   // pair of n8 frags
                    int r = wn * 32 + np * 16 + lr + ((g >> 1) << 3);
                    int c16 = k16 * 2 + (g & 1);
                    uint32_t ad = base + (uint32_t)(r * 128 + ((c16 ^ (r & 7)) << 4));
                    uint32_t tmp[4];
                    ldsm_x4(tmp, ad + OFF_BH);
                    bh[np * 2 + 0][0] = tmp[0]; bh[np * 2 + 0][1] = tmp[1];
                    bh[np * 2 + 1][0] = tmp[2]; bh[np * 2 + 1][1] = tmp[3];
                    ldsm_x4(tmp, ad + OFF_BL);
                    bl[np * 2 + 0][0] = tmp[0]; bl[np * 2 + 0][1] = tmp[1];
                    bl[np * 2 + 1][0] = tmp[2]; bl[np * 2 + 1][1] = tmp[3];
                }
            }
            // ---- 3-split MMA ----
            #pragma unroll
            for (int ms = 0; ms < 2; ++ms)
                #pragma unroll
                for (int ns = 0; ns < 4; ++ns) {
                    mma_bf16(acc[ms][ns], ah[ms], bh[ns]);
                    mma_bf16(acc[ms][ns], ah[ms], bl[ns]);
                    mma_bf16(acc[ms][ns], al[ms], bh[ns]);
                }
        }
        __syncthreads();
    }

    // ---- epilogue: acc -> smem D (aliases stages), then LSTM cell ----
    float* D = (float*)smem;
    {
        const int wrow = lane >> 2;
        const int wcol = (lane & 3) * 2;
        #pragma unroll
        for (int ms = 0; ms < 2; ++ms)
            #pragma unroll
            for (int ns = 0; ns < 4; ++ns) {
                int r0 = wm * 32 + ms * 16 + wrow;
                int cc = wn * 32 + ns * 8 + wcol;
                *(float2*)&D[r0 * DS + cc]       = make_float2(acc[ms][ns][0], acc[ms][ns][1]);
                *(float2*)&D[(r0 + 8) * DS + cc] = make_float2(acc[ms][ns][2], acc[ms][ns][3]);
            }
    }
    __syncthreads();

    #pragma unroll
    for (int i = 0; i < 8; ++i) {
        int id = tid + i * 256;
        int r = id >> 5, q = id & 31;
        int b = m0 + r, j = j0 + q;
        int l  = lseq[b * SEQ + t];
        int st = sseq[b * SEQ + t];
        const float4 L = *(const float4*)&g_lp_r[(size_t)l  * GATES + (size_t)j * 4];
        const float4 S = *(const float4*)&g_sp_r[(size_t)st * GATES + (size_t)j * 4];
        float4 z = *(const float4*)&D[r * DS + q * 4];
        float zi = z.x + L.x + S.x;
        float zf = z.y + L.y + S.y;
        float zg = z.z + L.z + S.z;
        float zo = z.w + L.w + S.w;
        float ig = sigf(zi), fg = sigf(zf);
        float gg = tanh_(zg), og = sigf(zo);
        float cp = out_c[(size_t)b * SH + (size_t)(t - 1) * HID + j];
        float c = fg * cp + ig * gg;
        float h = og * tanh_(c);
        out_h[(size_t)b * SH + (size_t)t * HID + j] = h;
        out_c[(size_t)b * SH + (size_t)t * HID + j] = c;
        __nv_bfloat16 hh = __float2bfloat16(h);
        hw_hi[(size_t)b * HID + j] = hh;
        hw_lo[(size_t)b * HID + j] = __float2bfloat16(h - __bfloat162float(hh));
    }
}

// ---------------------------------------------------------------------------
extern "C" void kernel_launch(void* const* d_in, const int* in_sizes, int n_in,
                              void* d_out, int out_size) {
    const int*   lseq = (const int*)d_in[0];
    const int*   sseq = (const int*)d_in[1];
    const float* lemb = (const float*)d_in[2];
    const float* semb = (const float*)d_in[3];
    const float* W_ih = (const float*)d_in[4];
    const float* W_hh = (const float*)d_in[5];
    const float* b_ih = (const float*)d_in[6];
    const float* b_hh = (const float*)d_in[7];
    float* out = (float*)d_out;

    static bool attr_set = false;
    if (!attr_set) {
        cudaFuncSetAttribute(step_kernel,
                             cudaFuncAttributeMaxDynamicSharedMemorySize, SMEM_TOTAL);
        attr_set = true;
    }

    proj_kernel<<<(GATES + 127) / 128, 128>>>(lemb, semb, W_ih, b_ih, b_hh);
    wsplit_kernel<<<2048, 256>>>(W_hh);

    dim3 grid(GATES / TN, BATCH / TM);   // 32 x 4 = 128 CTAs
    for (int t = 0; t < SEQ; ++t)
        step_kernel<<<grid, 256, SMEM_TOTAL>>>(lseq, sseq, out, t);
}

// round 4
// speedup vs baseline: 3.3427x; 1.0517x over previous
#include <cuda_runtime.h>
#include <cuda_bf16.h>
#include <cstdint>

// ---------------------------------------------------------------------------
// Problem constants
// ---------------------------------------------------------------------------
#define BATCH 256
#define SEQ   256
#define EMB   256
#define HID   1024
#define GATES 4096          // 4*HID
#define SH    (SEQ * HID)   // per-batch stride in out

// GEMM tiling
#define TM 64               // CTA M tile (batch)
#define TN 128              // CTA N tile (gate-cols, j-major)
#define KC 64               // K chunk (bf16)
#define NCHUNK (HID / KC)   // 16

// SMEM stage layout: Ah | Al | Bh | Bl   (3 stages)
#define OFF_AH 0
#define OFF_AL 8192         // 64*64*2
#define OFF_BH 16384
#define OFF_BL 32768        // Bh = 128*64*2 = 16384
#define STAGE  49152
#define NSTAGE 3
#define SMEM_TOTAL (NSTAGE * STAGE)   // 144 KB; epilogue D aliases stage 0

#define DS 132              // D smem row stride (floats)

// ---------------------------------------------------------------------------
// Device-global precomputed state
// ---------------------------------------------------------------------------
__device__ float g_lp_r[30 * GATES];   // n = j*4 + gate
__device__ float g_sp_r[4 * GATES];
__device__ __nv_bfloat16 g_W_hi[(size_t)GATES * HID];   // row n = j*4+g
__device__ __nv_bfloat16 g_W_lo[(size_t)GATES * HID];
__device__ __nv_bfloat16 g_h_hi[2][(size_t)BATCH * HID];
__device__ __nv_bfloat16 g_h_lo[2][(size_t)BATCH * HID];

// ---------------------------------------------------------------------------
// PTX helpers (Ampere-era: valid at compute_103)
// ---------------------------------------------------------------------------
__device__ __forceinline__ uint32_t smem_u32(const void* p) {
    uint32_t a;
    asm("{ .reg .u64 t; cvta.to.shared.u64 t, %1; cvt.u32.u64 %0, t; }"
        : "=r"(a) : "l"(p));
    return a;
}
#define CP16(dst, src) \
    asm volatile("cp.async.cg.shared.global [%0], [%1], 16;" :: "r"(dst), "l"(src))
#define CP_COMMIT() asm volatile("cp.async.commit_group;" ::: "memory")
#define CP_WAIT(n)  asm volatile("cp.async.wait_group %0;" :: "n"(n) : "memory")

__device__ __forceinline__ void ldsm_x4(uint32_t (&r)[4], uint32_t addr) {
    asm volatile("ldmatrix.sync.aligned.m8n8.x4.shared.b16 {%0,%1,%2,%3}, [%4];"
                 : "=r"(r[0]), "=r"(r[1]), "=r"(r[2]), "=r"(r[3]) : "r"(addr));
}
__device__ __forceinline__ void mma_bf16(float (&d)[4], const uint32_t (&a)[4],
                                         const uint32_t* b) {
    asm volatile(
        "mma.sync.aligned.m16n8k16.row.col.f32.bf16.bf16.f32 "
        "{%0,%1,%2,%3}, {%4,%5,%6,%7}, {%8,%9}, {%0,%1,%2,%3};"
        : "+f"(d[0]), "+f"(d[1]), "+f"(d[2]), "+f"(d[3])
        : "r"(a[0]), "r"(a[1]), "r"(a[2]), "r"(a[3]), "r"(b[0]), "r"(b[1]));
}

__device__ __forceinline__ float sigf(float x) {
    float e = __expf(-x);
    return __fdividef(1.0f, 1.0f + e);
}
__device__ __forceinline__ float tanh_(float x) {
    float e = __expf(-2.0f * x);
    return __fdividef(1.0f - e, 1.0f + e);
}

// ---------------------------------------------------------------------------
// Precompute 1: reordered projection tables
// ---------------------------------------------------------------------------
__global__ void proj_kernel(const float* __restrict__ letter_emb,
                            const float* __restrict__ state_emb,
                            const float* __restrict__ W_ih,
                            const float* __restrict__ b_ih,
                            const float* __restrict__ b_hh) {
    int r = blockIdx.x * blockDim.x + threadIdx.x;
    if (r >= GATES) return;
    int gate = r / HID, j = r % HID;
    int n = j * 4 + gate;
    const float* wl = W_ih + (size_t)r * (2 * EMB);
    const float* ws = wl + EMB;

    for (int l = 0; l < 30; ++l) {
        const float* e = letter_emb + l * EMB;
        float s = 0.0f;
        #pragma unroll 8
        for (int k = 0; k < EMB; ++k) s += e[k] * wl[k];
        g_lp_r[l * GATES + n] = s;
    }
    float bias = b_ih[r] + b_hh[r];
    for (int st = 0; st < 4; ++st) {
        const float* e = state_emb + st * EMB;
        float s = bias;
        #pragma unroll 8
        for (int k = 0; k < EMB; ++k) s += e[k] * ws[k];
        g_sp_r[st * GATES + n] = s;
    }
}

// ---------------------------------------------------------------------------
// Precompute 2: W_hh reorder + bf16 hi/lo split
// ---------------------------------------------------------------------------
__global__ void wsplit_kernel(const float* __restrict__ W_hh) {
    size_t idx = (size_t)blockIdx.x * blockDim.x + threadIdx.x;
    size_t total = (size_t)GATES * HID;
    for (; idx < total; idx += (size_t)gridDim.x * blockDim.x) {
        int n = (int)(idx >> 10);
        int k = (int)(idx & 1023);
        int j = n >> 2, g = n & 3;
        float w = W_hh[((size_t)g * HID + j) * HID + k];
        __nv_bfloat16 hi = __float2bfloat16(w);
        g_W_hi[idx] = hi;
        g_W_lo[idx] = __float2bfloat16(w - __bfloat162float(hi));
    }
}

// ---------------------------------------------------------------------------
// Fragment set for one k16 slice (warp tile 32x32, 3-split bf16)
// ---------------------------------------------------------------------------
struct Frags {
    uint32_t ah[2][4], al[2][4];
    uint32_t bh[4][2], bl[4][2];
};

// ---------------------------------------------------------------------------
// One LSTM timestep via warp-level bf16x3 HMMA, 3-stage pipeline
// ---------------------------------------------------------------------------
__global__ void __launch_bounds__(256, 1)
step_kernel(const int* __restrict__ lseq,
            const int* __restrict__ sseq,
            float* __restrict__ out, int t) {
    extern __shared__ char smem[];
    const int tid  = threadIdx.x;
    const int wid  = tid >> 5;
    const int lane = tid & 31;
    const int wm   = wid >> 2;     // 0..1
    const int wn   = wid & 3;      // 0..3
    const int m0   = blockIdx.y * TM;
    const int n0c  = blockIdx.x * TN;
    const int j0   = n0c >> 2;

    float* __restrict__ out_h = out;
    float* __restrict__ out_c = out + (size_t)BATCH * SH;
    __nv_bfloat16* __restrict__ hw_hi = g_h_hi[t & 1];
    __nv_bfloat16* __restrict__ hw_lo = g_h_lo[t & 1];

    if (t == 0) {
        for (int u = tid; u < TM * 32; u += 256) {
            int r = u >> 5, q = u & 31;
            int b = m0 + r, j = j0 + q;
            int l  = lseq[b * SEQ];
            int st = sseq[b * SEQ];
            const float4 L = *(const float4*)&g_lp_r[(size_t)l  * GATES + (size_t)j * 4];
            const float4 S = *(const float4*)&g_sp_r[(size_t)st * GATES + (size_t)j * 4];
            float ig = sigf(L.x + S.x);
            float gg = tanh_(L.z + S.z);
            float og = sigf(L.w + S.w);
            float c = ig * gg;
            float h = og * tanh_(c);
            out_h[(size_t)b * SH + j] = h;
            out_c[(size_t)b * SH + j] = c;
            __nv_bfloat16 hh = __float2bfloat16(h);
            hw_hi[(size_t)b * HID + j] = hh;
            hw_lo[(size_t)b * HID + j] = __float2bfloat16(h - __bfloat162float(hh));
        }
        return;
    }

    const uint32_t sb = smem_u32(smem);
    const __nv_bfloat16* __restrict__ ha_hi = g_h_hi[(t & 1) ^ 1] + (size_t)m0 * HID;
    const __nv_bfloat16* __restrict__ ha_lo = g_h_lo[(t & 1) ^ 1] + (size_t)m0 * HID;
    const __nv_bfloat16* __restrict__ wb_hi = g_W_hi + (size_t)n0c * HID;
    const __nv_bfloat16* __restrict__ wb_lo = g_W_lo + (size_t)n0c * HID;

    float acc[2][4][4];
    #pragma unroll
    for (int ms = 0; ms < 2; ++ms)
        #pragma unroll
        for (int ns = 0; ns < 4; ++ns)
            #pragma unroll
            for (int q = 0; q < 4; ++q) acc[ms][ns][q] = 0.0f;

    // ---- chunk loader: 12 x 16B cp.async per thread ----
    auto load_chunk = [&](uint32_t buf, int k0) {
        #pragma unroll
        for (int i = 0; i < 2; ++i) {
            int id = tid + i * 256;
            int r = id >> 3, c = id & 7;
            uint32_t dst = buf + (uint32_t)(r * 128 + ((c ^ (r & 7)) << 4));
            CP16(dst + OFF_AH, ha_hi + (size_t)r * HID + k0 + c * 8);
            CP16(dst + OFF_AL, ha_lo + (size_t)r * HID + k0 + c * 8);
        }
        #pragma unroll
        for (int i = 0; i < 4; ++i) {
            int id = tid + i * 256;
            int r = id >> 3, c = id & 7;
            uint32_t dst = buf + (uint32_t)(r * 128 + ((c ^ (r & 7)) << 4));
            CP16(dst + OFF_BH, wb_hi + (size_t)r * HID + k0 + c * 8);
            CP16(dst + OFF_BL, wb_lo + (size_t)r * HID + k0 + c * 8);
        }
    };

    // ---- frag loader for one k16 slice ----
    const int g_  = lane >> 3;
    const int lr_ = lane & 7;
    auto load_frags = [&](Frags& f, uint32_t base, int k16) {
        #pragma unroll
        for (int ms = 0; ms < 2; ++ms) {
            int r = wm * 32 + ms * 16 + lr_ + ((g_ & 1) << 3);
            int c16 = k16 * 2 + (g_ >> 1);
            uint32_t ad = base + (uint32_t)(r * 128 + ((c16 ^ (r & 7)) << 4));
            ldsm_x4(f.ah[ms], ad + OFF_AH);
            ldsm_x4(f.al[ms], ad + OFF_AL);
        }
        #pragma unroll
        for (int np = 0; np < 2; ++np) {
            int r = wn * 32 + np * 16 + lr_ + ((g_ >> 1) << 3);
            int c16 = k16 * 2 + (g_ & 1);
            uint32_t ad = base + (uint32_t)(r * 128 + ((c16 ^ (r & 7)) << 4));
            uint32_t tmp[4];
            ldsm_x4(tmp, ad + OFF_BH);
            f.bh[np * 2 + 0][0] = tmp[0]; f.bh[np * 2 + 0][1] = tmp[1];
            f.bh[np * 2 + 1][0] = tmp[2]; f.bh[np * 2 + 1][1] = tmp[3];
            ldsm_x4(tmp, ad + OFF_BL);
            f.bl[np * 2 + 0][0] = tmp[0]; f.bl[np * 2 + 0][1] = tmp[1];
            f.bl[np * 2 + 1][0] = tmp[2]; f.bl[np * 2 + 1][1] = tmp[3];
        }
    };
    auto mma_all = [&](const Frags& f) {
        #pragma unroll
        for (int ms = 0; ms < 2; ++ms)
            #pragma unroll
            for (int ns = 0; ns < 4; ++ns) {
                mma_bf16(acc[ms][ns], f.ah[ms], f.bh[ns]);
                mma_bf16(acc[ms][ns], f.ah[ms], f.bl[ns]);
                mma_bf16(acc[ms][ns], f.al[ms], f.bh[ns]);
            }
    };

    // ---- prologue: stages 0 and 1 in flight ----
    load_chunk(sb + 0 * STAGE, 0);
    CP_COMMIT();
    load_chunk(sb + 1 * STAGE, KC);
    CP_COMMIT();

    Frags f[2];
    int stage_w = 2;   // next stage slot to write (rotates 0,1,2)
    int stage_r = 0;   // stage holding chunk kc

    for (int kc = 0; kc < NCHUNK; ++kc) {
        CP_WAIT(1);          // chunk kc complete (this thread's groups)
        __syncthreads();     // visibility + closes WAR window on stage_w
        if (kc + 2 < NCHUNK)
            load_chunk(sb + stage_w * STAGE, (kc + 2) * KC);
        CP_COMMIT();         // possibly empty group: keeps wait arithmetic uniform

        const uint32_t base = sb + stage_r * STAGE;
        load_frags(f[0], base, 0);
        #pragma unroll
        for (int k16 = 0; k16 < 4; ++k16) {
            if (k16 < 3) load_frags(f[(k16 + 1) & 1], base, k16 + 1);
            mma_all(f[k16 & 1]);
        }
        stage_r = (stage_r == 2) ? 0 : stage_r + 1;
        stage_w = (stage_w == 2) ? 0 : stage_w + 1;
    }
    __syncthreads();   // all MMAs done before D aliases stage 0

    // ---- epilogue: acc -> smem D, then LSTM cell ----
    float* D = (float*)smem;
    {
        const int wrow = lane >> 2;
        const int wcol = (lane & 3) * 2;
        #pragma unroll
        for (int ms = 0; ms < 2; ++ms)
            #pragma unroll
            for (int ns = 0; ns < 4; ++ns) {
                int r0 = wm * 32 + ms * 16 + wrow;
                int cc = wn * 32 + ns * 8 + wcol;
                *(float2*)&D[r0 * DS + cc]       = make_float2(acc[ms][ns][0], acc[ms][ns][1]);
                *(float2*)&D[(r0 + 8) * DS + cc] = make_float2(acc[ms][ns][2], acc[ms][ns][3]);
            }
    }
    __syncthreads();

    #pragma unroll
    for (int i = 0; i < 8; ++i) {
        int id = tid + i * 256;
        int r = id >> 5, q = id & 31;
        int b = m0 + r, j = j0 + q;
        int l  = lseq[b * SEQ + t];
        int st = sseq[b * SEQ + t];
        const float4 L = *(const float4*)&g_lp_r[(size_t)l  * GATES + (size_t)j * 4];
        const float4 S = *(const float4*)&g_sp_r[(size_t)st * GATES + (size_t)j * 4];
        float4 z = *(const float4*)&D[r * DS + q * 4];
        float zi = z.x + L.x + S.x;
        float zf = z.y + L.y + S.y;
        float zg = z.z + L.z + S.z;
        float zo = z.w + L.w + S.w;
        float ig = sigf(zi), fg = sigf(zf);
        float gg = tanh_(zg), og = sigf(zo);
        float cp = out_c[(size_t)b * SH + (size_t)(t - 1) * HID + j];
        float c = fg * cp + ig * gg;
        float h = og * tanh_(c);
        out_h[(size_t)b * SH + (size_t)t * HID + j] = h;
        out_c[(size_t)b * SH + (size_t)t * HID + j] = c;
        __nv_bfloat16 hh = __float2bfloat16(h);
        hw_hi[(size_t)b * HID + j] = hh;
        hw_lo[(size_t)b * HID + j] = __float2bfloat16(h - __bfloat162float(hh));
    }
}

// ---------------------------------------------------------------------------
extern "C" void kernel_launch(void* const* d_in, const int* in_sizes, int n_in,
                              void* d_out, int out_size) {
    const int*   lseq = (const int*)d_in[0];
    const int*   sseq = (const int*)d_in[1];
    const float* lemb = (const float*)d_in[2];
    const float* semb = (const float*)d_in[3];
    const float* W_ih = (const float*)d_in[4];
    const float* W_hh = (const float*)d_in[5];
    const float* b_ih = (const float*)d_in[6];
    const float* b_hh = (const float*)d_in[7];
    float* out = (float*)d_out;

    static bool attr_set = false;
    if (!attr_set) {
        cudaFuncSetAttribute(step_kernel,
                             cudaFuncAttributeMaxDynamicSharedMemorySize, SMEM_TOTAL);
        attr_set = true;
    }

    proj_kernel<<<(GATES + 127) / 128, 128>>>(lemb, semb, W_ih, b_ih, b_hh);
    wsplit_kernel<<<2048, 256>>>(W_hh);

    dim3 grid(GATES / TN, BATCH / TM);   // 32 x 4 = 128 CTAs
    for (int t = 0; t < SEQ; ++t)
        step_kernel<<<grid, 256, SMEM_TOTAL>>>(lseq, sseq, out, t);
}

// round 5
// speedup vs baseline: 3.3690x; 1.0079x over previous
#include <cuda_runtime.h>
#include <cuda_bf16.h>
#include <cstdint>

// ---------------------------------------------------------------------------
// Problem constants
// ---------------------------------------------------------------------------
#define BATCH 256
#define SEQ   256
#define EMB   256
#define HID   1024
#define GATES 4096          // 4*HID
#define SH    (SEQ * HID)   // per-batch stride in out

// GEMM tiling
#define TM 64               // CTA M tile (batch)
#define TN 128              // CTA N tile (gate-cols, j-major)
#define KC 64               // K chunk (bf16)
#define NCHUNK (HID / KC)   // 16

// SMEM stage layout: Ah | Al | Bh | Bl   (3 stages)
#define OFF_AH 0
#define OFF_AL 8192         // 64*64*2
#define OFF_BH 16384
#define OFF_BL 32768        // Bh = 128*64*2 = 16384
#define STAGE  49152
#define NSTAGE 3
#define SMEM_TOTAL (NSTAGE * STAGE)   // 144 KB; epilogue D aliases stage 0

#define DS 132              // D smem row stride (floats)

// ---------------------------------------------------------------------------
// Device-global precomputed state
// ---------------------------------------------------------------------------
__device__ float g_lp_r[30 * GATES];   // n = j*4 + gate
__device__ float g_sp_r[4 * GATES];
__device__ __nv_bfloat16 g_W_hi[(size_t)GATES * HID];   // row n = j*4+g
__device__ __nv_bfloat16 g_W_lo[(size_t)GATES * HID];
__device__ __nv_bfloat16 g_h_hi[2][(size_t)BATCH * HID];
__device__ __nv_bfloat16 g_h_lo[2][(size_t)BATCH * HID];

// ---------------------------------------------------------------------------
// PTX helpers (Ampere-era: valid at compute_103)
// ---------------------------------------------------------------------------
__device__ __forceinline__ uint32_t smem_u32(const void* p) {
    uint32_t a;
    asm("{ .reg .u64 t; cvta.to.shared.u64 t, %1; cvt.u32.u64 %0, t; }"
        : "=r"(a) : "l"(p));
    return a;
}
#define CP16(dst, src) \
    asm volatile("cp.async.cg.shared.global [%0], [%1], 16;" :: "r"(dst), "l"(src))
#define CP_COMMIT() asm volatile("cp.async.commit_group;" ::: "memory")
#define CP_WAIT(n)  asm volatile("cp.async.wait_group %0;" :: "n"(n) : "memory")

__device__ __forceinline__ void ldsm_x4(uint32_t (&r)[4], uint32_t addr) {
    asm volatile("ldmatrix.sync.aligned.m8n8.x4.shared.b16 {%0,%1,%2,%3}, [%4];"
                 : "=r"(r[0]), "=r"(r[1]), "=r"(r[2]), "=r"(r[3]) : "r"(addr));
}
__device__ __forceinline__ void mma_bf16(float (&d)[4], const uint32_t (&a)[4],
                                         const uint32_t* b) {
    asm volatile(
        "mma.sync.aligned.m16n8k16.row.col.f32.bf16.bf16.f32 "
        "{%0,%1,%2,%3}, {%4,%5,%6,%7}, {%8,%9}, {%0,%1,%2,%3};"
        : "+f"(d[0]), "+f"(d[1]), "+f"(d[2]), "+f"(d[3])
        : "r"(a[0]), "r"(a[1]), "r"(a[2]), "r"(a[3]), "r"(b[0]), "r"(b[1]));
}

__device__ __forceinline__ float sigf(float x) {
    float e = __expf(-x);
    return __fdividef(1.0f, 1.0f + e);
}
__device__ __forceinline__ float tanh_(float x) {
    float e = __expf(-2.0f * x);
    return __fdividef(1.0f - e, 1.0f + e);
}

// ---------------------------------------------------------------------------
// Precompute 1: reordered projection tables
// ---------------------------------------------------------------------------
__global__ void proj_kernel(const float* __restrict__ letter_emb,
                            const float* __restrict__ state_emb,
                            const float* __restrict__ W_ih,
                            const float* __restrict__ b_ih,
                            const float* __restrict__ b_hh) {
    int r = blockIdx.x * blockDim.x + threadIdx.x;
    if (r >= GATES) return;
    int gate = r / HID, j = r % HID;
    int n = j * 4 + gate;
    const float* wl = W_ih + (size_t)r * (2 * EMB);
    const float* ws = wl + EMB;

    for (int l = 0; l < 30; ++l) {
        const float* e = letter_emb + l * EMB;
        float s = 0.0f;
        #pragma unroll 8
        for (int k = 0; k < EMB; ++k) s += e[k] * wl[k];
        g_lp_r[l * GATES + n] = s;
    }
    float bias = b_ih[r] + b_hh[r];
    for (int st = 0; st < 4; ++st) {
        const float* e = state_emb + st * EMB;
        float s = bias;
        #pragma unroll 8
        for (int k = 0; k < EMB; ++k) s += e[k] * ws[k];
        g_sp_r[st * GATES + n] = s;
    }
}

// ---------------------------------------------------------------------------
// Precompute 2: W_hh reorder + bf16 hi/lo split
// ---------------------------------------------------------------------------
__global__ void wsplit_kernel(const float* __restrict__ W_hh) {
    size_t idx = (size_t)blockIdx.x * blockDim.x + threadIdx.x;
    size_t total = (size_t)GATES * HID;
    for (; idx < total; idx += (size_t)gridDim.x * blockDim.x) {
        int n = (int)(idx >> 10);
        int k = (int)(idx & 1023);
        int j = n >> 2, g = n & 3;
        float w = W_hh[((size_t)g * HID + j) * HID + k];
        __nv_bfloat16 hi = __float2bfloat16(w);
        g_W_hi[idx] = hi;
        g_W_lo[idx] = __float2bfloat16(w - __bfloat162float(hi));
    }
}

// ---------------------------------------------------------------------------
// Fragment set for one k16 slice (warp tile 32x32, 3-split bf16)
// ---------------------------------------------------------------------------
struct Frags {
    uint32_t ah[2][4], al[2][4];
    uint32_t bh[4][2], bl[4][2];
};

// ---------------------------------------------------------------------------
// One LSTM timestep via warp-level bf16x3 HMMA, 3-stage pipeline
// ---------------------------------------------------------------------------
__global__ void __launch_bounds__(256, 1)
step_kernel(const int* __restrict__ lseq,
            const int* __restrict__ sseq,
            float* __restrict__ out, int t) {
    extern __shared__ char smem[];
    const int tid  = threadIdx.x;
    const int wid  = tid >> 5;
    const int lane = tid & 31;
    const int wm   = wid >> 2;     // 0..1
    const int wn   = wid & 3;      // 0..3
    const int m0   = blockIdx.y * TM;
    const int n0c  = blockIdx.x * TN;
    const int j0   = n0c >> 2;

    float* __restrict__ out_h = out;
    float* __restrict__ out_c = out + (size_t)BATCH * SH;
    __nv_bfloat16* __restrict__ hw_hi = g_h_hi[t & 1];
    __nv_bfloat16* __restrict__ hw_lo = g_h_lo[t & 1];

    if (t == 0) {
        for (int u = tid; u < TM * 32; u += 256) {
            int r = u >> 5, q = u & 31;
            int b = m0 + r, j = j0 + q;
            int l  = lseq[b * SEQ];
            int st = sseq[b * SEQ];
            const float4 L = *(const float4*)&g_lp_r[(size_t)l  * GATES + (size_t)j * 4];
            const float4 S = *(const float4*)&g_sp_r[(size_t)st * GATES + (size_t)j * 4];
            float ig = sigf(L.x + S.x);
            float gg = tanh_(L.z + S.z);
            float og = sigf(L.w + S.w);
            float c = ig * gg;
            float h = og * tanh_(c);
            out_h[(size_t)b * SH + j] = h;
            out_c[(size_t)b * SH + j] = c;
            __nv_bfloat16 hh = __float2bfloat16(h);
            hw_hi[(size_t)b * HID + j] = hh;
            hw_lo[(size_t)b * HID + j] = __float2bfloat16(h - __bfloat162float(hh));
        }
        return;
    }

    const uint32_t sb = smem_u32(smem);
    const __nv_bfloat16* __restrict__ ha_hi = g_h_hi[(t & 1) ^ 1] + (size_t)m0 * HID;
    const __nv_bfloat16* __restrict__ ha_lo = g_h_lo[(t & 1) ^ 1] + (size_t)m0 * HID;
    const __nv_bfloat16* __restrict__ wb_hi = g_W_hi + (size_t)n0c * HID;
    const __nv_bfloat16* __restrict__ wb_lo = g_W_lo + (size_t)n0c * HID;

    float acc[2][4][4];
    #pragma unroll
    for (int ms = 0; ms < 2; ++ms)
        #pragma unroll
        for (int ns = 0; ns < 4; ++ns)
            #pragma unroll
            for (int q = 0; q < 4; ++q) acc[ms][ns][q] = 0.0f;

    // ---- chunk loader: 12 x 16B cp.async per thread ----
    auto load_chunk = [&](uint32_t buf, int k0) {
        #pragma unroll
        for (int i = 0; i < 2; ++i) {
            int id = tid + i * 256;
            int r = id >> 3, c = id & 7;
            uint32_t dst = buf + (uint32_t)(r * 128 + ((c ^ (r & 7)) << 4));
            CP16(dst + OFF_AH, ha_hi + (size_t)r * HID + k0 + c * 8);
            CP16(dst + OFF_AL, ha_lo + (size_t)r * HID + k0 + c * 8);
        }
        #pragma unroll
        for (int i = 0; i < 4; ++i) {
            int id = tid + i * 256;
            int r = id >> 3, c = id & 7;
            uint32_t dst = buf + (uint32_t)(r * 128 + ((c ^ (r & 7)) << 4));
            CP16(dst + OFF_BH, wb_hi + (size_t)r * HID + k0 + c * 8);
            CP16(dst + OFF_BL, wb_lo + (size_t)r * HID + k0 + c * 8);
        }
    };

    // ---- frag loader for one k16 slice ----
    const int g_  = lane >> 3;
    const int lr_ = lane & 7;
    auto load_frags = [&](Frags& f, uint32_t base, int k16) {
        #pragma unroll
        for (int ms = 0; ms < 2; ++ms) {
            int r = wm * 32 + ms * 16 + lr_ + ((g_ & 1) << 3);
            int c16 = k16 * 2 + (g_ >> 1);
            uint32_t ad = base + (uint32_t)(r * 128 + ((c16 ^ (r & 7)) << 4));
            ldsm_x4(f.ah[ms], ad + OFF_AH);
            ldsm_x4(f.al[ms], ad + OFF_AL);
        }
        #pragma unroll
        for (int np = 0; np < 2; ++np) {
            int r = wn * 32 + np * 16 + lr_ + ((g_ >> 1) << 3);
            int c16 = k16 * 2 + (g_ & 1);
            uint32_t ad = base + (uint32_t)(r * 128 + ((c16 ^ (r & 7)) << 4));
            uint32_t tmp[4];
            ldsm_x4(tmp, ad + OFF_BH);
            f.bh[np * 2 + 0][0] = tmp[0]; f.bh[np * 2 + 0][1] = tmp[1];
            f.bh[np * 2 + 1][0] = tmp[2]; f.bh[np * 2 + 1][1] = tmp[3];
            ldsm_x4(tmp, ad + OFF_BL);
            f.bl[np * 2 + 0][0] = tmp[0]; f.bl[np * 2 + 0][1] = tmp[1];
            f.bl[np * 2 + 1][0] = tmp[2]; f.bl[np * 2 + 1][1] = tmp[3];
        }
    };

    // ---- split-major MMA issue: acc reuse distance = 8 MMAs (was 1) ----
    auto mma_all = [&](const Frags& f) {
        #pragma unroll
        for (int ms = 0; ms < 2; ++ms)
            #pragma unroll
            for (int ns = 0; ns < 4; ++ns)
                mma_bf16(acc[ms][ns], f.ah[ms], f.bh[ns]);
        #pragma unroll
        for (int ms = 0; ms < 2; ++ms)
            #pragma unroll
            for (int ns = 0; ns < 4; ++ns)
                mma_bf16(acc[ms][ns], f.ah[ms], f.bl[ns]);
        #pragma unroll
        for (int ms = 0; ms < 2; ++ms)
            #pragma unroll
            for (int ns = 0; ns < 4; ++ns)
                mma_bf16(acc[ms][ns], f.al[ms], f.bh[ns]);
    };

    // ---- prologue: stages 0 and 1 in flight ----
    load_chunk(sb + 0 * STAGE, 0);
    CP_COMMIT();
    load_chunk(sb + 1 * STAGE, KC);
    CP_COMMIT();

    Frags f[2];
    int stage_w = 2;   // next stage slot to write (rotates 0,1,2)
    int stage_r = 0;   // stage holding chunk kc

    for (int kc = 0; kc < NCHUNK; ++kc) {
        CP_WAIT(1);          // chunk kc complete (this thread's groups)
        __syncthreads();     // visibility + closes WAR window on stage_w
        if (kc + 2 < NCHUNK)
            load_chunk(sb + stage_w * STAGE, (kc + 2) * KC);
        CP_COMMIT();         // possibly empty group: keeps wait arithmetic uniform

        const uint32_t base = sb + stage_r * STAGE;
        load_frags(f[0], base, 0);
        #pragma unroll
        for (int k16 = 0; k16 < 4; ++k16) {
            if (k16 < 3) load_frags(f[(k16 + 1) & 1], base, k16 + 1);
            mma_all(f[k16 & 1]);
        }
        stage_r = (stage_r == 2) ? 0 : stage_r + 1;
        stage_w = (stage_w == 2) ? 0 : stage_w + 1;
    }
    __syncthreads();   // all MMAs done before D aliases stage 0

    // ---- epilogue: acc -> smem D, then LSTM cell ----
    float* D = (float*)smem;
    {
        const int wrow = lane >> 2;
        const int wcol = (lane & 3) * 2;
        #pragma unroll
        for (int ms = 0; ms < 2; ++ms)
            #pragma unroll
            for (int ns = 0; ns < 4; ++ns) {
                int r0 = wm * 32 + ms * 16 + wrow;
                int cc = wn * 32 + ns * 8 + wcol;
                *(float2*)&D[r0 * DS + cc]       = make_float2(acc[ms][ns][0], acc[ms][ns][1]);
                *(float2*)&D[(r0 + 8) * DS + cc] = make_float2(acc[ms][ns][2], acc[ms][ns][3]);
            }
    }
    __syncthreads();

    #pragma unroll
    for (int i = 0; i < 8; ++i) {
        int id = tid + i * 256;
        int r = id >> 5, q = id & 31;
        int b = m0 + r, j = j0 + q;
        int l  = lseq[b * SEQ + t];
        int st = sseq[b * SEQ + t];
        const float4 L = *(const float4*)&g_lp_r[(size_t)l  * GATES + (size_t)j * 4];
        const float4 S = *(const float4*)&g_sp_r[(size_t)st * GATES + (size_t)j * 4];
        float4 z = *(const float4*)&D[r * DS + q * 4];
        float zi = z.x + L.x + S.x;
        float zf = z.y + L.y + S.y;
        float zg = z.z + L.z + S.z;
        float zo = z.w + L.w + S.w;
        float ig = sigf(zi), fg = sigf(zf);
        float gg = tanh_(zg), og = sigf(zo);
        float cp = out_c[(size_t)b * SH + (size_t)(t - 1) * HID + j];
        float c = fg * cp + ig * gg;
        float h = og * tanh_(c);
        out_h[(size_t)b * SH + (size_t)t * HID + j] = h;
        out_c[(size_t)b * SH + (size_t)t * HID + j] = c;
        __nv_bfloat16 hh = __float2bfloat16(h);
        hw_hi[(size_t)b * HID + j] = hh;
        hw_lo[(size_t)b * HID + j] = __float2bfloat16(h - __bfloat162float(hh));
    }
}

// ---------------------------------------------------------------------------
extern "C" void kernel_launch(void* const* d_in, const int* in_sizes, int n_in,
                              void* d_out, int out_size) {
    const int*   lseq = (const int*)d_in[0];
    const int*   sseq = (const int*)d_in[1];
    const float* lemb = (const float*)d_in[2];
    const float* semb = (const float*)d_in[3];
    const float* W_ih = (const float*)d_in[4];
    const float* W_hh = (const float*)d_in[5];
    const float* b_ih = (const float*)d_in[6];
    const float* b_hh = (const float*)d_in[7];
    float* out = (float*)d_out;

    static bool attr_set = false;
    if (!attr_set) {
        cudaFuncSetAttribute(step_kernel,
                             cudaFuncAttributeMaxDynamicSharedMemorySize, SMEM_TOTAL);
        attr_set = true;
    }

    proj_kernel<<<(GATES + 127) / 128, 128>>>(lemb, semb, W_ih, b_ih, b_hh);
    wsplit_kernel<<<2048, 256>>>(W_hh);

    dim3 grid(GATES / TN, BATCH / TM);   // 32 x 4 = 128 CTAs
    for (int t = 0; t < SEQ; ++t)
        step_kernel<<<grid, 256, SMEM_TOTAL>>>(lseq, sseq, out, t);
}

// round 6
// speedup vs baseline: 5.7285x; 1.7003x over previous
#include <cuda_runtime.h>
#include <cuda_fp16.h>
#include <cuda_bf16.h>
#include <cstdint>

// ---------------------------------------------------------------------------
// Problem constants
// ---------------------------------------------------------------------------
#define BATCH 256
#define SEQ   256
#define EMB   256
#define HID   1024
#define GATES 4096          // 4*HID
#define SH    (SEQ * HID)   // per-batch stride in out

// GEMM tiling
#define TM 64               // CTA M tile (batch)
#define TN 128              // CTA N tile (gate-cols, j-major)
#define KC 64               // K chunk (fp16)
#define NCHUNK (HID / KC)   // 16

// SMEM stage layout: Ah | Bh   (3 stages)
#define OFF_AH 0
#define OFF_BH 8192         // Ah = 64*64*2
#define STAGE  24576        // + Bh = 128*64*2
#define NSTAGE 3
#define SMEM_TOTAL (NSTAGE * STAGE)   // 72 KB; epilogue D aliases stage 0

#define DS 132              // D smem row stride (floats)

// ---------------------------------------------------------------------------
// Device-global precomputed state
// ---------------------------------------------------------------------------
__device__ float g_lp_r[30 * GATES];   // n = j*4 + gate
__device__ float g_sp_r[4 * GATES];
__device__ __half g_W_h[(size_t)GATES * HID];   // row n = j*4+g, fp16
__device__ __half g_h[2][(size_t)BATCH * HID];  // h scratch, fp16 ping-pong

// ---------------------------------------------------------------------------
// PTX helpers (Ampere-era: valid at compute_103)
// ---------------------------------------------------------------------------
__device__ __forceinline__ uint32_t smem_u32(const void* p) {
    uint32_t a;
    asm("{ .reg .u64 t; cvta.to.shared.u64 t, %1; cvt.u32.u64 %0, t; }"
        : "=r"(a) : "l"(p));
    return a;
}
#define CP16(dst, src) \
    asm volatile("cp.async.cg.shared.global [%0], [%1], 16;" :: "r"(dst), "l"(src))
#define CP_COMMIT() asm volatile("cp.async.commit_group;" ::: "memory")
#define CP_WAIT(n)  asm volatile("cp.async.wait_group %0;" :: "n"(n) : "memory")

__device__ __forceinline__ void ldsm_x4(uint32_t (&r)[4], uint32_t addr) {
    asm volatile("ldmatrix.sync.aligned.m8n8.x4.shared.b16 {%0,%1,%2,%3}, [%4];"
                 : "=r"(r[0]), "=r"(r[1]), "=r"(r[2]), "=r"(r[3]) : "r"(addr));
}
__device__ __forceinline__ void mma_f16(float (&d)[4], const uint32_t (&a)[4],
                                        const uint32_t* b) {
    asm volatile(
        "mma.sync.aligned.m16n8k16.row.col.f32.f16.f16.f32 "
        "{%0,%1,%2,%3}, {%4,%5,%6,%7}, {%8,%9}, {%0,%1,%2,%3};"
        : "+f"(d[0]), "+f"(d[1]), "+f"(d[2]), "+f"(d[3])
        : "r"(a[0]), "r"(a[1]), "r"(a[2]), "r"(a[3]), "r"(b[0]), "r"(b[1]));
}

__device__ __forceinline__ float sigf(float x) {
    float e = __expf(-x);
    return __fdividef(1.0f, 1.0f + e);
}
__device__ __forceinline__ float tanh_(float x) {
    float e = __expf(-2.0f * x);
    return __fdividef(1.0f - e, 1.0f + e);
}

// ---------------------------------------------------------------------------
// Precompute 1: reordered projection tables
// ---------------------------------------------------------------------------
__global__ void proj_kernel(const float* __restrict__ letter_emb,
                            const float* __restrict__ state_emb,
                            const float* __restrict__ W_ih,
                            const float* __restrict__ b_ih,
                            const float* __restrict__ b_hh) {
    int r = blockIdx.x * blockDim.x + threadIdx.x;
    if (r >= GATES) return;
    int gate = r / HID, j = r % HID;
    int n = j * 4 + gate;
    const float* wl = W_ih + (size_t)r * (2 * EMB);
    const float* ws = wl + EMB;

    for (int l = 0; l < 30; ++l) {
        const float* e = letter_emb + l * EMB;
        float s = 0.0f;
        #pragma unroll 8
        for (int k = 0; k < EMB; ++k) s += e[k] * wl[k];
        g_lp_r[l * GATES + n] = s;
    }
    float bias = b_ih[r] + b_hh[r];
    for (int st = 0; st < 4; ++st) {
        const float* e = state_emb + st * EMB;
        float s = bias;
        #pragma unroll 8
        for (int k = 0; k < EMB; ++k) s += e[k] * ws[k];
        g_sp_r[st * GATES + n] = s;
    }
}

// ---------------------------------------------------------------------------
// Precompute 2: W_hh reorder + fp16 convert
// ---------------------------------------------------------------------------
__global__ void wconv_kernel(const float* __restrict__ W_hh) {
    size_t idx = (size_t)blockIdx.x * blockDim.x + threadIdx.x;
    size_t total = (size_t)GATES * HID;
    for (; idx < total; idx += (size_t)gridDim.x * blockDim.x) {
        int n = (int)(idx >> 10);
        int k = (int)(idx & 1023);
        int j = n >> 2, g = n & 3;
        g_W_h[idx] = __float2half(W_hh[((size_t)g * HID + j) * HID + k]);
    }
}

// ---------------------------------------------------------------------------
// Fragment set for one k16 slice (warp tile 32x32, fp16 single)
// ---------------------------------------------------------------------------
struct Frags {
    uint32_t ah[2][4];
    uint32_t bh[4][2];
};

// ---------------------------------------------------------------------------
// One LSTM timestep via warp-level fp16 HMMA, 3-stage pipeline
// ---------------------------------------------------------------------------
__global__ void __launch_bounds__(256, 1)
step_kernel(const int* __restrict__ lseq,
            const int* __restrict__ sseq,
            float* __restrict__ out, int t) {
    extern __shared__ char smem[];
    const int tid  = threadIdx.x;
    const int wid  = tid >> 5;
    const int lane = tid & 31;
    const int wm   = wid >> 2;     // 0..1
    const int wn   = wid & 3;      // 0..3
    const int m0   = blockIdx.y * TM;
    const int n0c  = blockIdx.x * TN;
    const int j0   = n0c >> 2;

    float* __restrict__ out_h = out;
    float* __restrict__ out_c = out + (size_t)BATCH * SH;
    __half* __restrict__ hw = g_h[t & 1];

    if (t == 0) {
        for (int u = tid; u < TM * 32; u += 256) {
            int r = u >> 5, q = u & 31;
            int b = m0 + r, j = j0 + q;
            int l  = lseq[b * SEQ];
            int st = sseq[b * SEQ];
            const float4 L = *(const float4*)&g_lp_r[(size_t)l  * GATES + (size_t)j * 4];
            const float4 S = *(const float4*)&g_sp_r[(size_t)st * GATES + (size_t)j * 4];
            float ig = sigf(L.x + S.x);
            float gg = tanh_(L.z + S.z);
            float og = sigf(L.w + S.w);
            float c = ig * gg;
            float h = og * tanh_(c);
            out_h[(size_t)b * SH + j] = h;
            out_c[(size_t)b * SH + j] = c;
            hw[(size_t)b * HID + j] = __float2half(h);
        }
        return;
    }

    const uint32_t sb = smem_u32(smem);
    const __half* __restrict__ ha = g_h[(t & 1) ^ 1] + (size_t)m0 * HID;
    const __half* __restrict__ wb = g_W_h + (size_t)n0c * HID;

    float acc[2][4][4];
    #pragma unroll
    for (int ms = 0; ms < 2; ++ms)
        #pragma unroll
        for (int ns = 0; ns < 4; ++ns)
            #pragma unroll
            for (int q = 0; q < 4; ++q) acc[ms][ns][q] = 0.0f;

    // ---- chunk loader: 6 x 16B cp.async per thread ----
    auto load_chunk = [&](uint32_t buf, int k0) {
        #pragma unroll
        for (int i = 0; i < 2; ++i) {
            int id = tid + i * 256;
            int r = id >> 3, c = id & 7;
            uint32_t dst = buf + (uint32_t)(r * 128 + ((c ^ (r & 7)) << 4));
            CP16(dst + OFF_AH, ha + (size_t)r * HID + k0 + c * 8);
        }
        #pragma unroll
        for (int i = 0; i < 4; ++i) {
            int id = tid + i * 256;
            int r = id >> 3, c = id & 7;
            uint32_t dst = buf + (uint32_t)(r * 128 + ((c ^ (r & 7)) << 4));
            CP16(dst + OFF_BH, wb + (size_t)r * HID + k0 + c * 8);
        }
    };

    // ---- frag loader for one k16 slice ----
    const int g_  = lane >> 3;
    const int lr_ = lane & 7;
    auto load_frags = [&](Frags& f, uint32_t base, int k16) {
        #pragma unroll
        for (int ms = 0; ms < 2; ++ms) {
            int r = wm * 32 + ms * 16 + lr_ + ((g_ & 1) << 3);
            int c16 = k16 * 2 + (g_ >> 1);
            uint32_t ad = base + (uint32_t)(r * 128 + ((c16 ^ (r & 7)) << 4));
            ldsm_x4(f.ah[ms], ad + OFF_AH);
        }
        #pragma unroll
        for (int np = 0; np < 2; ++np) {
            int r = wn * 32 + np * 16 + lr_ + ((g_ >> 1) << 3);
            int c16 = k16 * 2 + (g_ & 1);
            uint32_t ad = base + (uint32_t)(r * 128 + ((c16 ^ (r & 7)) << 4));
            uint32_t tmp[4];
            ldsm_x4(tmp, ad + OFF_BH);
            f.bh[np * 2 + 0][0] = tmp[0]; f.bh[np * 2 + 0][1] = tmp[1];
            f.bh[np * 2 + 1][0] = tmp[2]; f.bh[np * 2 + 1][1] = tmp[3];
        }
    };
    auto mma_all = [&](const Frags& f) {
        #pragma unroll
        for (int ms = 0; ms < 2; ++ms)
            #pragma unroll
            for (int ns = 0; ns < 4; ++ns)
                mma_f16(acc[ms][ns], f.ah[ms], f.bh[ns]);
    };

    // ---- prologue: stages 0 and 1 in flight ----
    load_chunk(sb + 0 * STAGE, 0);
    CP_COMMIT();
    load_chunk(sb + 1 * STAGE, KC);
    CP_COMMIT();

    Frags f[2];
    int stage_w = 2;   // next stage slot to write (rotates 0,1,2)
    int stage_r = 0;   // stage holding chunk kc

    for (int kc = 0; kc < NCHUNK; ++kc) {
        CP_WAIT(1);          // chunk kc complete
        __syncthreads();     // visibility + closes WAR window on stage_w
        if (kc + 2 < NCHUNK)
            load_chunk(sb + stage_w * STAGE, (kc + 2) * KC);
        CP_COMMIT();         // possibly empty: keeps wait arithmetic uniform

        const uint32_t base = sb + stage_r * STAGE;
        load_frags(f[0], base, 0);
        #pragma unroll
        for (int k16 = 0; k16 < 4; ++k16) {
            if (k16 < 3) load_frags(f[(k16 + 1) & 1], base, k16 + 1);
            mma_all(f[k16 & 1]);
        }
        stage_r = (stage_r == 2) ? 0 : stage_r + 1;
        stage_w = (stage_w == 2) ? 0 : stage_w + 1;
    }
    __syncthreads();   // all MMAs done before D aliases stage 0

    // ---- epilogue: acc -> smem D, then LSTM cell ----
    float* D = (float*)smem;
    {
        const int wrow = lane >> 2;
        const int wcol = (lane & 3) * 2;
        #pragma unroll
        for (int ms = 0; ms < 2; ++ms)
            #pragma unroll
            for (int ns = 0; ns < 4; ++ns) {
                int r0 = wm * 32 + ms * 16 + wrow;
                int cc = wn * 32 + ns * 8 + wcol;
                *(float2*)&D[r0 * DS + cc]       = make_float2(acc[ms][ns][0], acc[ms][ns][1]);
                *(float2*)&D[(r0 + 8) * DS + cc] = make_float2(acc[ms][ns][2], acc[ms][ns][3]);
            }
    }
    __syncthreads();

    #pragma unroll
    for (int i = 0; i < 8; ++i) {
        int id = tid + i * 256;
        int r = id >> 5, q = id & 31;
        int b = m0 + r, j = j0 + q;
        int l  = lseq[b * SEQ + t];
        int st = sseq[b * SEQ + t];
        const float4 L = *(const float4*)&g_lp_r[(size_t)l  * GATES + (size_t)j * 4];
        const float4 S = *(const float4*)&g_sp_r[(size_t)st * GATES + (size_t)j * 4];
        float4 z = *(const float4*)&D[r * DS + q * 4];
        float zi = z.x + L.x + S.x;
        float zf = z.y + L.y + S.y;
        float zg = z.z + L.z + S.z;
        float zo = z.w + L.w + S.w;
        float ig = sigf(zi), fg = sigf(zf);
        float gg = tanh_(zg), og = sigf(zo);
        float cp = out_c[(size_t)b * SH + (size_t)(t - 1) * HID + j];
        float c = fg * cp + ig * gg;
        float h = og * tanh_(c);
        out_h[(size_t)b * SH + (size_t)t * HID + j] = h;
        out_c[(size_t)b * SH + (size_t)t * HID + j] = c;
        hw[(size_t)b * HID + j] = __float2half(h);
    }
}

// ---------------------------------------------------------------------------
extern "C" void kernel_launch(void* const* d_in, const int* in_sizes, int n_in,
                              void* d_out, int out_size) {
    const int*   lseq = (const int*)d_in[0];
    const int*   sseq = (const int*)d_in[1];
    const float* lemb = (const float*)d_in[2];
    const float* semb = (const float*)d_in[3];
    const float* W_ih = (const float*)d_in[4];
    const float* W_hh = (const float*)d_in[5];
    const float* b_ih = (const float*)d_in[6];
    const float* b_hh = (const float*)d_in[7];
    float* out = (float*)d_out;

    static bool attr_set = false;
    if (!attr_set) {
        cudaFuncSetAttribute(step_kernel,
                             cudaFuncAttributeMaxDynamicSharedMemorySize, SMEM_TOTAL);
        attr_set = true;
    }

    proj_kernel<<<(GATES + 127) / 128, 128>>>(lemb, semb, W_ih, b_ih, b_hh);
    wconv_kernel<<<2048, 256>>>(W_hh);

    dim3 grid(GATES / TN, BATCH / TM);   // 32 x 4 = 128 CTAs
    for (int t = 0; t < SEQ; ++t)
        step_kernel<<<grid, 256, SMEM_TOTAL>>>(lseq, sseq, out, t);
}